// round 5
// baseline (speedup 1.0000x reference)
#include <cuda_runtime.h>
#include <cuda_bf16.h>
#include <cstdint>

#define NUM_ITER 10
#define MU_      (1.0f/256.0f)
#define EPS_     1e-8f
#define CEXP     (-28.853900817779268f)   /* -(1/tau)*log2(e) */
#define CLOG     (-0.034657359027997264f) /* -tau*ln(2): cost = CLOG*log2(K) */

#define BSTR      272
#define KSTR      528
#define B_OFF     0
#define K_OFF     69632
#define S2_OFF    204800
#define T2_OFF    205824
#define U_OFF     206848
#define V_OFF     207872
#define RED_OFF   208896                   /* 16 warps * 4B plus pad */
#define UBF_OFF   209920
#define VBF_OFF   210432
#define SMEM_TOTAL 210944

__device__ __forceinline__ uint32_t smem_u32(const void* p) {
    uint32_t a;
    asm("{ .reg .u64 t; cvta.to.shared.u64 t, %1; cvt.u32.u64 %0, t; }" : "=r"(a) : "l"(p));
    return a;
}
__device__ __forceinline__ float fsqrt_ap(float x) { float r; asm("sqrt.approx.f32 %0, %1;" : "=f"(r) : "f"(x)); return r; }
__device__ __forceinline__ float fex2_ap (float x) { float r; asm("ex2.approx.f32 %0, %1;"  : "=f"(r) : "f"(x)); return r; }
__device__ __forceinline__ float flg2_ap (float x) { float r; asm("lg2.approx.f32 %0, %1;"  : "=f"(r) : "f"(x)); return r; }
__device__ __forceinline__ float frcp_ap (float x) { float r; asm("rcp.approx.f32 %0, %1;"  : "=f"(r) : "f"(x)); return r; }
__device__ __forceinline__ float bf_lo(uint32_t w) { return __uint_as_float(w << 16); }
__device__ __forceinline__ float bf_hi(uint32_t w) { return __uint_as_float(w & 0xffff0000u); }
__device__ __forceinline__ uint32_t b2u(__nv_bfloat162 h) { return *reinterpret_cast<uint32_t*>(&h); }
__device__ __forceinline__ uint32_t pack_bf(float a, float b) { return b2u(__floats2bfloat162_rn(a, b)); }

__device__ __forceinline__ void mma16816(float* c, const uint32_t* a, uint32_t b0, uint32_t b1) {
    asm volatile(
        "mma.sync.aligned.m16n8k16.row.col.f32.bf16.bf16.f32 "
        "{%0,%1,%2,%3}, {%4,%5,%6,%7}, {%8,%9}, {%0,%1,%2,%3};"
        : "+f"(c[0]), "+f"(c[1]), "+f"(c[2]), "+f"(c[3])
        : "r"(a[0]), "r"(a[1]), "r"(a[2]), "r"(a[3]), "r"(b0), "r"(b1));
}
__device__ __forceinline__ void ldsm4(uint32_t* r, uint32_t addr) {
    asm volatile("ldmatrix.sync.aligned.m8n8.x4.shared.b16 {%0,%1,%2,%3}, [%4];"
        : "=r"(r[0]), "=r"(r[1]), "=r"(r[2]), "=r"(r[3]) : "r"(addr));
}
__device__ __forceinline__ void ldsm4t(uint32_t* r, uint32_t addr) {
    asm volatile("ldmatrix.sync.aligned.m8n8.x4.trans.shared.b16 {%0,%1,%2,%3}, [%4];"
        : "=r"(r[0]), "=r"(r[1]), "=r"(r[2]), "=r"(r[3]) : "r"(addr));
}

__device__ float g_partial[1024];
__device__ int   g_count = 0;

__global__ void __launch_bounds__(512, 1)
sinkhorn_kernel(const float* __restrict__ src, const float* __restrict__ tgt,
                float* __restrict__ out) {
    extern __shared__ char sm[];
    const int tid = threadIdx.x, wid = tid >> 5, lane = tid & 31;
    const int g = lane >> 2, t = lane & 3;
    const int bt = blockIdx.x;

    float* s2arr = (float*)(sm + S2_OFF);
    float* t2arr = (float*)(sm + T2_OFF);
    float* uarr  = (float*)(sm + U_OFF);
    float* varr  = (float*)(sm + V_OFF);
    float* red   = (float*)(sm + RED_OFF);
    __nv_bfloat16* vbf = (__nv_bfloat16*)(sm + VBF_OFF);
    __nv_bfloat16* ubf = (__nv_bfloat16*)(sm + UBF_OFF);
    const uint32_t* ubf32 = (const uint32_t*)(sm + UBF_OFF);
    const uint32_t* vbf32 = (const uint32_t*)(sm + VBF_OFF);

    /* ---- phase 1a: tgt -> smem bf16 [n][k]; t2 row sums ---- */
    {
        const float4* t4 = reinterpret_cast<const float4*>(tgt) + (size_t)bt * 8192;
        #pragma unroll 4
        for (int j = 0; j < 16; j++) {
            int row = 16 * j + wid;
            float4 f = t4[row * 32 + lane];
            float ss = f.x*f.x + f.y*f.y + f.z*f.z + f.w*f.w;
            #pragma unroll
            for (int o = 16; o > 0; o >>= 1) ss += __shfl_xor_sync(0xffffffffu, ss, o);
            if (lane == 0) t2arr[row] = ss;
            *reinterpret_cast<uint2*>(sm + B_OFF + row * BSTR + lane * 8) =
                make_uint2(pack_bf(f.x, f.y), pack_bf(f.z, f.w));
        }
    }

    /* ---- phase 1b: src -> register A fragments (1 m-tile/warp); s2 sums ---- */
    uint32_t afrag[8][4];
    {
        const float2* a2 = reinterpret_cast<const float2*>(src) + (size_t)bt * 16384;
        const int r0 = 16 * wid + g, r1 = r0 + 8;
        float s0 = 0.0f, s1 = 0.0f;
        #pragma unroll
        for (int ks = 0; ks < 8; ks++) {
            int kk = 8 * ks + t;
            float2 f00 = a2[r0 * 64 + kk];
            float2 f10 = a2[r1 * 64 + kk];
            float2 f01 = a2[r0 * 64 + kk + 4];
            float2 f11 = a2[r1 * 64 + kk + 4];
            afrag[ks][0] = pack_bf(f00.x, f00.y);
            afrag[ks][1] = pack_bf(f10.x, f10.y);
            afrag[ks][2] = pack_bf(f01.x, f01.y);
            afrag[ks][3] = pack_bf(f11.x, f11.y);
            s0 += f00.x*f00.x + f00.y*f00.y + f01.x*f01.x + f01.y*f01.y;
            s1 += f10.x*f10.x + f10.y*f10.y + f11.x*f11.x + f11.y*f11.y;
        }
        s0 += __shfl_xor_sync(0xffffffffu, s0, 1); s0 += __shfl_xor_sync(0xffffffffu, s0, 2);
        s1 += __shfl_xor_sync(0xffffffffu, s1, 1); s1 += __shfl_xor_sync(0xffffffffu, s1, 2);
        if (t == 0) { s2arr[r0] = s0; s2arr[r1] = s1; }
    }
    if (tid < 256) vbf[tid] = __float2bfloat16(1.0f);
    __syncthreads();

    /* ---- phase 2: HMMA GEMM fused with cost -> K(bf16) ---- */
    {
        const int r0 = 16 * wid + g, r1 = r0 + 8;
        const float s20 = s2arr[r0], s21 = s2arr[r1];
        char* kb = sm + K_OFF;
        #pragma unroll 2
        for (int nt = 0; nt < 32; nt++) {
            const char* bp = sm + B_OFF + (nt * 8 + g) * BSTR + 4 * t;
            float acc[4] = {0.f, 0.f, 0.f, 0.f};
            #pragma unroll
            for (int ks = 0; ks < 8; ks++) {
                uint32_t b0 = *reinterpret_cast<const uint32_t*>(bp + 32 * ks);
                uint32_t b1 = *reinterpret_cast<const uint32_t*>(bp + 32 * ks + 16);
                mma16816(acc, afrag[ks], b0, b1);
            }
            int c0 = nt * 8 + 2 * t;
            float t20 = t2arr[c0], t21 = t2arr[c0 + 1];
            float x;
            x = fmaxf(s20 + t20 - 2.0f * acc[0], 0.0f); float k00 = fex2_ap(fsqrt_ap(x) * CEXP);
            x = fmaxf(s20 + t21 - 2.0f * acc[1], 0.0f); float k01 = fex2_ap(fsqrt_ap(x) * CEXP);
            x = fmaxf(s21 + t20 - 2.0f * acc[2], 0.0f); float k10 = fex2_ap(fsqrt_ap(x) * CEXP);
            x = fmaxf(s21 + t21 - 2.0f * acc[3], 0.0f); float k11 = fex2_ap(fsqrt_ap(x) * CEXP);
            *reinterpret_cast<uint32_t*>(kb + r0 * KSTR + 2 * c0) = pack_bf(k00, k01);
            *reinterpret_cast<uint32_t*>(kb + r1 * KSTR + 2 * c0) = pack_bf(k10, k11);
        }
    }
    __syncthreads();

    /* ---- phase 3: 10 Sinkhorn iterations, matvecs via HMMA ---- */
    {
        const uint32_t kb32 = smem_u32(sm + K_OFF);
        const int l7 = lane & 7, q = lane >> 3;
        const uint32_t ua_base = kb32 + (16 * wid + l7 + (q & 1) * 8) * KSTR + ((q >> 1) * 8) * 2;
        const uint32_t va_base = kb32 + (l7 + (q >> 1) * 8) * KSTR + (16 * wid + (q & 1) * 8) * 2;

        for (int it = 0; it < NUM_ITER; it++) {
            /* u = mu / (K v + eps) */
            float acc[4] = {0.f, 0.f, 0.f, 0.f};
            #pragma unroll
            for (int s = 0; s < 16; s++) {
                uint32_t a[4];
                ldsm4(a, ua_base + s * 32);
                mma16816(acc, a, vbf32[8 * s + t], vbf32[8 * s + t + 4]);
            }
            if (t == 0) {
                int r = 16 * wid + g;
                float u0 = MU_ * frcp_ap(acc[0] + EPS_);
                float u1 = MU_ * frcp_ap(acc[2] + EPS_);
                uarr[r] = u0; uarr[r + 8] = u1;
                ubf[r] = __float2bfloat16(u0); ubf[r + 8] = __float2bfloat16(u1);
            }
            __syncthreads();
            /* v = mu / (K^T u + eps) */
            float c[4] = {0.f, 0.f, 0.f, 0.f};
            #pragma unroll
            for (int s = 0; s < 16; s++) {
                uint32_t a[4];
                ldsm4t(a, va_base + s * (16 * KSTR));
                mma16816(c, a, ubf32[8 * s + t], ubf32[8 * s + t + 4]);
            }
            if (t == 0) {
                int cc = 16 * wid + g;
                float v0 = MU_ * frcp_ap(c[0] + EPS_);
                float v1 = MU_ * frcp_ap(c[2] + EPS_);
                varr[cc] = v0; varr[cc + 8] = v1;
                vbf[cc] = __float2bfloat16(v0); vbf[cc + 8] = __float2bfloat16(v1);
            }
            __syncthreads();
        }
    }

    /* ---- phase 4: loss = sum u K v cost, cost = CLOG * log2(K) ---- */
    {
        const int row = tid >> 1, half = tid & 1;
        const uint4* krow4 = reinterpret_cast<const uint4*>(sm + K_OFF + (size_t)row * KSTR) + half * 16;
        const float4* v4 = reinterpret_cast<const float4*>(varr) + half * 32;
        float acc = 0.0f;
        #pragma unroll
        for (int j = 0; j < 16; j++) {
            uint4 q4 = krow4[j];
            float4 va = v4[2 * j], vb = v4[2 * j + 1];
            float k0, k1;
            k0 = bf_lo(q4.x); k1 = bf_hi(q4.x);
            acc += k0 * va.x * flg2_ap(k0) + k1 * va.y * flg2_ap(k1);
            k0 = bf_lo(q4.y); k1 = bf_hi(q4.y);
            acc += k0 * va.z * flg2_ap(k0) + k1 * va.w * flg2_ap(k1);
            k0 = bf_lo(q4.z); k1 = bf_hi(q4.z);
            acc += k0 * vb.x * flg2_ap(k0) + k1 * vb.y * flg2_ap(k1);
            k0 = bf_lo(q4.w); k1 = bf_hi(q4.w);
            acc += k0 * vb.z * flg2_ap(k0) + k1 * vb.w * flg2_ap(k1);
        }
        acc *= uarr[row] * CLOG;
        #pragma unroll
        for (int o = 16; o > 0; o >>= 1) acc += __shfl_xor_sync(0xffffffffu, acc, o);
        if (lane == 0) red[wid] = acc;
        __syncthreads();
        if (tid == 0) {
            float tsum = 0.0f;
            #pragma unroll
            for (int w = 0; w < 16; w++) tsum += red[w];
            g_partial[bt] = tsum;
        }
    }

    /* ---- phase 5: last block reduces g_partial -> out (single-launch design) ---- */
    __shared__ int is_last;
    if (tid == 0) {
        __threadfence();
        int c = atomicAdd(&g_count, 1);
        is_last = (c == 1023);
    }
    __syncthreads();
    if (is_last) {
        if (tid == 0) g_count = 0;                      /* reset for next call */
        float s = g_partial[tid] + g_partial[tid + 512];
        #pragma unroll
        for (int o = 16; o > 0; o >>= 1) s += __shfl_xor_sync(0xffffffffu, s, o);
        if (lane == 0) red[wid] = s;
        __syncthreads();
        if (tid == 0) {
            float tsum = 0.0f;
            #pragma unroll
            for (int w = 0; w < 16; w++) tsum += red[w];
            out[0] = tsum * (1.0f / 1024.0f);
        }
    }
}

extern "C" void kernel_launch(void* const* d_in, const int* in_sizes, int n_in,
                              void* d_out, int out_size) {
    const float* src = (const float*)d_in[0];
    const float* tgt = (const float*)d_in[1];
    float* out = (float*)d_out;
    cudaFuncSetAttribute(sinkhorn_kernel, cudaFuncAttributeMaxDynamicSharedMemorySize, SMEM_TOTAL);
    sinkhorn_kernel<<<1024, 512, SMEM_TOTAL>>>(src, tgt, out);
}